// round 4
// baseline (speedup 1.0000x reference)
#include <cuda_runtime.h>
#include <cuda_bf16.h>
#include <cstdint>

// ---------------------------------------------------------------------------
// Problem constants
// ---------------------------------------------------------------------------
#define BT 4096
#define HDIM 2048
#define VOCAB 32000
#define TILE_M 128                         // per CTA; pair tile M = 256
#define TILE_N 256                         // pair tile N (128 B-rows per CTA)
#define K_CHUNK 64
#define N_KCHUNKS (HDIM / K_CHUNK)        // 32
#define M_PAIRS (BT / 256)                 // 16
#define N_TILES (VOCAB / TILE_N)           // 125
#define IGNORE_INDEX (-100LL)
#define RL_BLOCKS 16

// idesc kind::f16 cg2: dtype=F32(1<<4), atype=BF16(1<<7), btype=BF16(1<<10),
// N/8<<17, M_total/16<<24  (matches working test_2cta_mma_bf16 example)
#define MMA_IDESC ((1u << 4) | (1u << 7) | (1u << 10) | ((TILE_N / 8) << 17) | ((256 / 16) << 24))

// SMEM layout (dynamic). Per CTA: A half 128x64bf16 = 16KB x2 bufs, B half same.
#define SM_TMEMPTR 0
#define SM_MMABAR0 8
#define SM_MMABAR1 16
#define SM_FILL0 24
#define SM_FILL1 32
#define SM_A 1024
#define SM_B (1024 + 2 * 16384)            // 33792
#define SM_TOTAL (SM_B + 2 * 16384)        // 66560

#if defined(__CUDA_ARCH_FEAT_SM103_ALL) || defined(__CUDA_ARCH_FEAT_SM100_ALL)
#define HAS_TCGEN05 1
#else
#define HAS_TCGEN05 0
#endif

// ---------------------------------------------------------------------------
// Device scratch
// ---------------------------------------------------------------------------
__device__ __nv_bfloat16 g_hid_bf[(size_t)BT * HDIM];
__device__ __nv_bfloat16 g_w_bf[(size_t)VOCAB * HDIM];
__device__ float g_partials[(size_t)N_TILES * BT];
__device__ float g_tgt[BT];
__device__ float g_blocksum[RL_BLOCKS];
__device__ int   g_blockcnt[RL_BLOCKS];

// ---------------------------------------------------------------------------
// PTX helpers
// ---------------------------------------------------------------------------
__device__ __forceinline__ uint32_t smem_to_u32(const void* p) {
    uint32_t a;
    asm("{ .reg .u64 t; cvta.to.shared.u64 t, %1; cvt.u32.u64 %0, t; }" : "=r"(a) : "l"(p));
    return a;
}
__device__ __forceinline__ uint32_t elect_one_pred() {
    uint32_t pred;
    asm volatile("{\n\t.reg .pred p;\n\telect.sync _|p, 0xFFFFFFFF;\n\tselp.b32 %0, 1, 0, p;\n\t}" : "=r"(pred));
    return pred;
}
__device__ __forceinline__ uint32_t cluster_ctarank_u32() {
    uint32_t r;
    asm("mov.u32 %0, %%cluster_ctarank;" : "=r"(r));
    return r;
}
#define TCGEN05_ALLOC_CG2(smem_addr, nCols) \
    asm volatile("tcgen05.alloc.cta_group::2.sync.aligned.shared::cta.b32 [%0], %1;" \
                 :: "r"((uint32_t)(smem_addr)), "r"((uint32_t)(nCols)) : "memory")
#define TCGEN05_DEALLOC_CG2(tmem_addr, nCols) \
    asm volatile("tcgen05.dealloc.cta_group::2.sync.aligned.b32 %0, %1;" :: "r"(tmem_addr), "r"((uint32_t)(nCols)))
#define TCGEN05_RELINQUISH_CG2() \
    asm volatile("tcgen05.relinquish_alloc_permit.cta_group::2.sync.aligned;")
#define TCGEN05_FENCE_AFTER() asm volatile("tcgen05.fence::after_thread_sync;" ::: "memory")
#define TCGEN05_FENCE_BEFORE() asm volatile("tcgen05.fence::before_thread_sync;" ::: "memory")
#define TCGEN05_WAIT_LD() asm volatile("tcgen05.wait::ld.sync.aligned;" ::: "memory")
#define FENCE_PROXY_ASYNC_SHARED() asm volatile("fence.proxy.async.shared::cta;" ::: "memory")
#define MBARRIER_INIT(mbar, cnt) \
    asm volatile("mbarrier.init.shared.b64 [%0], %1;" :: "r"((uint32_t)(mbar)), "r"((uint32_t)(cnt)) : "memory")
#define MBARRIER_INVAL(mbar) \
    asm volatile("mbarrier.inval.shared.b64 [%0];" :: "r"((uint32_t)(mbar)) : "memory")
#define CLUSTER_SYNC() do { \
    asm volatile("barrier.cluster.arrive.aligned;" ::: "memory"); \
    asm volatile("barrier.cluster.wait.aligned;" ::: "memory"); \
} while (0)
// arrive on the same-offset mbarrier in cluster CTA `rank` (release, cluster scope)
#define MBARRIER_ARRIVE_CLUSTER(local_mbar, target_rank) \
    asm volatile("{\n\t.reg .b32 remAddr;\n\t" \
        "mapa.shared::cluster.u32 remAddr, %0, %1;\n\t" \
        "mbarrier.arrive.release.cluster.shared::cluster.b64 _, [remAddr];\n\t}" \
        :: "r"((uint32_t)(local_mbar)), "r"((uint32_t)(target_rank)) : "memory")
// cta-scope acquire wait (for locally-produced signals: multicast commit)
#define MBARRIER_WAIT_PARITY(mbar, parity) do {                                           \
    uint32_t _m = (uint32_t)(mbar); uint32_t _p = (uint32_t)(parity); uint32_t _d;        \
    asm volatile("{\n\t.reg .pred p;\n\t"                                                 \
        "mbarrier.try_wait.parity.acquire.cta.shared::cta.b64 p, [%1], %2;\n\t"           \
        "selp.b32 %0, 1, 0, p;\n\t}" : "=r"(_d) : "r"(_m), "r"(_p) : "memory");           \
    if (!_d) {                                                                            \
        asm volatile("{\n\t.reg .pred P1;\n\t"                                            \
            "WAIT_LOOP_%=:\n\t"                                                           \
            "mbarrier.try_wait.parity.acquire.cta.shared::cta.b64 P1, [%0], %1, 0x989680;\n\t" \
            "@P1 bra.uni WAIT_DONE_%=;\n\t"                                               \
            "bra.uni WAIT_LOOP_%=;\n\t"                                                   \
            "WAIT_DONE_%=:\n\t}" :: "r"(_m), "r"(_p) : "memory");                         \
    }                                                                                     \
} while (0)
// cluster-scope acquire wait (leader waiting for peer-CTA fill arrivals)
#define MBARRIER_WAIT_PARITY_CLU(mbar, parity) do {                                       \
    uint32_t _m = (uint32_t)(mbar); uint32_t _p = (uint32_t)(parity); uint32_t _d;        \
    asm volatile("{\n\t.reg .pred p;\n\t"                                                 \
        "mbarrier.try_wait.parity.acquire.cluster.shared::cta.b64 p, [%1], %2;\n\t"       \
        "selp.b32 %0, 1, 0, p;\n\t}" : "=r"(_d) : "r"(_m), "r"(_p) : "memory");           \
    if (!_d) {                                                                            \
        asm volatile("{\n\t.reg .pred P1;\n\t"                                            \
            "WAIT_LOOP_%=:\n\t"                                                           \
            "mbarrier.try_wait.parity.acquire.cluster.shared::cta.b64 P1, [%0], %1, 0x989680;\n\t" \
            "@P1 bra.uni WAIT_DONE_%=;\n\t"                                               \
            "bra.uni WAIT_LOOP_%=;\n\t"                                                   \
            "WAIT_DONE_%=:\n\t}" :: "r"(_m), "r"(_p) : "memory");                         \
    }                                                                                     \
} while (0)
#define TCGEN05_LD_32X32B_X32(r, tmem_addr) \
    asm volatile( \
        "tcgen05.ld.sync.aligned.32x32b.x32.b32 " \
        "{%0, %1, %2, %3, %4, %5, %6, %7, " \
        " %8, %9, %10, %11, %12, %13, %14, %15, " \
        " %16, %17, %18, %19, %20, %21, %22, %23, " \
        " %24, %25, %26, %27, %28, %29, %30, %31}, [%32];" \
        : "=r"((r)[0]),  "=r"((r)[1]),  "=r"((r)[2]),  "=r"((r)[3]), \
          "=r"((r)[4]),  "=r"((r)[5]),  "=r"((r)[6]),  "=r"((r)[7]), \
          "=r"((r)[8]),  "=r"((r)[9]),  "=r"((r)[10]), "=r"((r)[11]), \
          "=r"((r)[12]), "=r"((r)[13]), "=r"((r)[14]), "=r"((r)[15]), \
          "=r"((r)[16]), "=r"((r)[17]), "=r"((r)[18]), "=r"((r)[19]), \
          "=r"((r)[20]), "=r"((r)[21]), "=r"((r)[22]), "=r"((r)[23]), \
          "=r"((r)[24]), "=r"((r)[25]), "=r"((r)[26]), "=r"((r)[27]), \
          "=r"((r)[28]), "=r"((r)[29]), "=r"((r)[30]), "=r"((r)[31]) \
        : "r"(tmem_addr))

static constexpr uint64_t SMEM_DESC_BASE_SW128 =
    (uint64_t(2) << 61) | (uint64_t(1) << 46) | (uint64_t(64) << 32) | (uint64_t(1) << 16);
#define MAKE_SMEM_DESC(base_addr) (SMEM_DESC_BASE_SW128 | ((uint64_t)((base_addr) >> 4) & 0x3FFF))
#define SMEM_SWIZZLE_128B(off) ((off) ^ (((off) >> 3) & 0x70))

#if HAS_TCGEN05
// cg2 SS bf16 MMA (A from both CTAs' SMEM M-halves, B split N/2 per CTA)
__device__ __forceinline__ void mma_f16_ss_cg2(uint32_t d_tmem, uint64_t a_desc, uint64_t b_desc,
                                               uint32_t idesc, uint32_t enable_d) {
    asm volatile(
        "{\n\t.reg .pred p;\n\t"
        "setp.ne.u32 p, %5, 0;\n\t"
        "tcgen05.mma.cta_group::2.kind::f16 [%0], %1, %2, %3, {%4, %4, %4, %4, %4, %4, %4, %4}, p;\n\t}"
        :: "r"(d_tmem), "l"(a_desc), "l"(b_desc), "r"(idesc), "r"(0u), "r"(enable_d)
        : "memory");
}
#define TCGEN05_COMMIT_MC_CG2(mbar) \
    asm volatile("tcgen05.commit.cta_group::2.mbarrier::arrive::one.shared::cluster.multicast::cluster.b64 [%0], %1;" \
                 :: "r"((uint32_t)(mbar)), "h"((uint16_t)0x3) : "memory")
#endif

// ---------------------------------------------------------------------------
// Kernel 1: fp32 -> bf16 conversion (halves GEMM traffic)
// ---------------------------------------------------------------------------
__global__ void convert_kernel(const float* __restrict__ hid, const float* __restrict__ w) {
    const size_t nh = (size_t)BT * HDIM / 4;
    const size_t nw = (size_t)VOCAB * HDIM / 4;
    const size_t total = nh + nw;
    size_t stride = (size_t)gridDim.x * blockDim.x;
    for (size_t i = (size_t)blockIdx.x * blockDim.x + threadIdx.x; i < total; i += stride) {
        const float4* src;
        __nv_bfloat16* dst;
        size_t j;
        if (i < nh) { src = (const float4*)hid; dst = g_hid_bf; j = i; }
        else        { src = (const float4*)w;   dst = g_w_bf;   j = i - nh; }
        float4 v = src[j];
        __nv_bfloat162 lo = __floats2bfloat162_rn(v.x, v.y);
        __nv_bfloat162 hi = __floats2bfloat162_rn(v.z, v.w);
        *(__nv_bfloat162*)(dst + j * 4)     = lo;
        *(__nv_bfloat162*)(dst + j * 4 + 2) = hi;
    }
}

// ---------------------------------------------------------------------------
// Kernel 2: cg2 tcgen05 bf16 GEMM (256x256 pair tiles) + fused CE epilogue
// ---------------------------------------------------------------------------
__device__ __forceinline__ void load_chunk_half(char* smem, int tid,
                                                const __nv_bfloat16* Ag,
                                                const __nv_bfloat16* Bg,
                                                int k0, int buf) {
    // A half: 128 rows x 64 bf16 = 1024 uint4; B half: same
    char* abase = smem + SM_A + buf * 16384;
    char* bbase = smem + SM_B + buf * 16384;
#pragma unroll
    for (int l = 0; l < 8; l++) {
        int i = tid + l * 128;
        int row = i >> 3, c = i & 7;
        uint4 v = *(const uint4*)(Ag + (size_t)row * HDIM + k0 + c * 8);
        uint32_t off = row * 128 + c * 16;
        *(uint4*)(abase + SMEM_SWIZZLE_128B(off)) = v;
    }
#pragma unroll
    for (int l = 0; l < 8; l++) {
        int i = tid + l * 128;
        int row = i >> 3, c = i & 7;
        uint4 v = *(const uint4*)(Bg + (size_t)row * HDIM + k0 + c * 8);
        uint32_t off = row * 128 + c * 16;
        *(uint4*)(bbase + SMEM_SWIZZLE_128B(off)) = v;
    }
}

__global__ void __launch_bounds__(128)
__cluster_dims__(2, 1, 1)
gemm_ce_kernel(const long long* __restrict__ targets) {
    extern __shared__ char smem[];
    int tid = threadIdx.x;

    int pair = blockIdx.x >> 1;
    // consecutive pairs share the same 256-wide B panel -> L2 reuse within a wave
    int n_tile = pair / M_PAIRS;
    int m_pair = pair % M_PAIRS;
    int n0 = n_tile * TILE_N;

#if HAS_TCGEN05
    uint32_t rank = cluster_ctarank_u32();
    int m0_cta = m_pair * 256 + (int)rank * 128;   // this CTA's 128 A-rows
    uint32_t sb = smem_to_u32(smem);
    int wid = tid >> 5;

    if (wid == 0) TCGEN05_ALLOC_CG2(sb + SM_TMEMPTR, 256);
    __syncthreads();
    uint32_t tmem;
    asm volatile("ld.shared.b32 %0, [%1];" : "=r"(tmem) : "r"(sb + SM_TMEMPTR));

    if (tid == 0) {
        MBARRIER_INIT(sb + SM_MMABAR0, 1);
        MBARRIER_INIT(sb + SM_MMABAR1, 1);
        MBARRIER_INIT(sb + SM_FILL0, 2);   // both CTAs arrive; waited by leader only
        MBARRIER_INIT(sb + SM_FILL1, 2);
    }
    __syncthreads();
    CLUSTER_SYNC();  // peer mbarriers must be live before remote arrivals

    const __nv_bfloat16* Ag = g_hid_bf + (size_t)m0_cta * HDIM;
    const __nv_bfloat16* Bg = g_w_bf + (size_t)(n0 + (int)rank * 128) * HDIM;

    // prologue: fill buf0 with chunk 0, signal leader
    load_chunk_half(smem, tid, Ag, Bg, 0, 0);
    FENCE_PROXY_ASYNC_SHARED();
    __syncthreads();
    if (tid == 0) MBARRIER_ARRIVE_CLUSTER(sb + SM_FILL0, 0);

    int ph_mma0 = 0, ph_mma1 = 0;
    int ph_f0 = 0, ph_f1 = 0;  // leader-elect only

#pragma unroll 1
    for (int kc = 0; kc < N_KCHUNKS; kc++) {
        int cur = kc & 1;
        if (rank == 0 && wid == 0) {
            if (elect_one_pred()) {
                // wait both CTAs' fills of buffer `cur`
                if (cur == 0) { MBARRIER_WAIT_PARITY_CLU(sb + SM_FILL0, ph_f0); ph_f0 ^= 1; }
                else          { MBARRIER_WAIT_PARITY_CLU(sb + SM_FILL1, ph_f1); ph_f1 ^= 1; }
                TCGEN05_FENCE_AFTER();
                uint64_t ad = MAKE_SMEM_DESC(sb + SM_A + cur * 16384);
                uint64_t bd = MAKE_SMEM_DESC(sb + SM_B + cur * 16384);
#pragma unroll
                for (int s = 0; s < 4; s++)
                    mma_f16_ss_cg2(tmem, ad + s * 2, bd + s * 2, MMA_IDESC,
                                   (kc > 0 || s > 0) ? 1u : 0u);
                TCGEN05_COMMIT_MC_CG2(sb + (cur ? SM_MMABAR1 : SM_MMABAR0));
            }
        }
        if (kc + 1 < N_KCHUNKS) {
            int nxt = cur ^ 1;
            if (kc >= 1) {
                // buffer `nxt` must be done being read by the MMA of chunk kc-1
                if (nxt == 0) { MBARRIER_WAIT_PARITY(sb + SM_MMABAR0, ph_mma0); ph_mma0 ^= 1; }
                else          { MBARRIER_WAIT_PARITY(sb + SM_MMABAR1, ph_mma1); ph_mma1 ^= 1; }
            }
            load_chunk_half(smem, tid, Ag, Bg, (kc + 1) * K_CHUNK, nxt);
            FENCE_PROXY_ASYNC_SHARED();
            __syncthreads();
            if (tid == 0) MBARRIER_ARRIVE_CLUSTER(sb + (nxt ? SM_FILL1 : SM_FILL0), 0);
        }
    }
    // outstanding commits: chunk 30 (bar0), chunk 31 (bar1)
    MBARRIER_WAIT_PARITY(sb + SM_MMABAR0, ph_mma0);
    MBARRIER_WAIT_PARITY(sb + SM_MMABAR1, ph_mma1);
    TCGEN05_FENCE_AFTER();

    // Epilogue: this CTA's TMEM lanes = pair rows m_pair*256 + rank*128 + lane.
    int row = m0_cta + tid;
    long long t = targets[row];
    float sum = 0.0f;
    float tval = 0.0f;
#pragma unroll 1
    for (int c = 0; c < TILE_N / 32; c++) {
        uint32_t regs[32];
        TCGEN05_LD_32X32B_X32(regs, tmem + c * 32);
        TCGEN05_WAIT_LD();
#pragma unroll
        for (int j = 0; j < 32; j++) {
            float v = __uint_as_float(regs[j]);
            sum += __expf(v);
            if ((long long)(n0 + c * 32 + j) == t) tval = v;
        }
    }
    TCGEN05_FENCE_BEFORE();
    g_partials[(size_t)n_tile * BT + row] = sum;
    if (t >= (long long)n0 && t < (long long)(n0 + TILE_N)) g_tgt[row] = tval;

    __syncthreads();
    if (tid == 0) {
        MBARRIER_INVAL(sb + SM_MMABAR0);
        MBARRIER_INVAL(sb + SM_MMABAR1);
        MBARRIER_INVAL(sb + SM_FILL0);
        MBARRIER_INVAL(sb + SM_FILL1);
    }
    __syncthreads();
    if (wid == 0) {
        TCGEN05_RELINQUISH_CG2();
        TCGEN05_DEALLOC_CG2(tmem, 256);
    }
    CLUSTER_SYNC();  // no CTA exits while peer SMEM/TMEM still referenced

#else  // ------- non-sm_103a fallback (PTX-JIT path only) --------------------
    int rank = blockIdx.x & 1;
    int m0 = m_pair * 256 + rank * 128;
    __nv_bfloat16* As = (__nv_bfloat16*)smem;
    __nv_bfloat16* Bs = (__nv_bfloat16*)(smem + 16384);
    const __nv_bfloat16* Ag = g_hid_bf + (size_t)m0 * HDIM;

    long long t = targets[m0 + tid];
    float sum = 0.0f, tval = 0.0f;
    for (int cg = 0; cg < TILE_N / 32; cg++) {
        float acc[32];
#pragma unroll
        for (int j = 0; j < 32; j++) acc[j] = 0.0f;
        const __nv_bfloat16* Bg = g_w_bf + (size_t)(n0 + cg * 32) * HDIM;
        for (int kc = 0; kc < N_KCHUNKS; kc++) {
            __syncthreads();
            int k0 = kc * K_CHUNK;
#pragma unroll
            for (int l = 0; l < 8; l++) {
                int i = tid + l * 128;
                int r2 = i >> 3, c = i & 7;
                *(uint4*)(As + r2 * 64 + c * 8) =
                    *(const uint4*)(Ag + (size_t)r2 * HDIM + k0 + c * 8);
            }
#pragma unroll
            for (int l = 0; l < 2; l++) {
                int i = tid + l * 128;
                int r2 = i >> 3, c = i & 7;
                *(uint4*)(Bs + r2 * 64 + c * 8) =
                    *(const uint4*)(Bg + (size_t)r2 * HDIM + k0 + c * 8);
            }
            __syncthreads();
            for (int k = 0; k < K_CHUNK; k++) {
                float a = __bfloat162float(As[tid * 64 + k]);
#pragma unroll
                for (int j = 0; j < 32; j++)
                    acc[j] += a * __bfloat162float(Bs[j * 64 + k]);
            }
        }
#pragma unroll
        for (int j = 0; j < 32; j++) {
            float v = acc[j];
            sum += __expf(v);
            if ((long long)(n0 + cg * 32 + j) == t) tval = v;
        }
    }
    g_partials[(size_t)n_tile * BT + m0 + tid] = sum;
    if (t >= (long long)n0 && t < (long long)(n0 + TILE_N)) g_tgt[m0 + tid] = tval;
#endif
}

// ---------------------------------------------------------------------------
// Kernel 3a: per-row loss, whole-chip parallel, deterministic
// ---------------------------------------------------------------------------
__global__ void row_loss_kernel(const long long* __restrict__ targets) {
    __shared__ float sl[256];
    __shared__ int sc[256];
    int tid = threadIdx.x;
    int r = blockIdx.x * 256 + tid;

    float s = 0.0f;
#pragma unroll 5
    for (int nt = 0; nt < N_TILES; nt++) s += g_partials[(size_t)nt * BT + r];

    long long t = targets[r];
    bool valid = (t != IGNORE_INDEX);
    sl[tid] = valid ? (logf(s) - g_tgt[r]) : 0.0f;
    sc[tid] = valid ? 1 : 0;
    __syncthreads();
#pragma unroll
    for (int o = 128; o > 0; o >>= 1) {
        if (tid < o) { sl[tid] += sl[tid + o]; sc[tid] += sc[tid + o]; }
        __syncthreads();
    }
    if (tid == 0) { g_blocksum[blockIdx.x] = sl[0]; g_blockcnt[blockIdx.x] = sc[0]; }
}

// ---------------------------------------------------------------------------
// Kernel 3b: final scalar combine
// ---------------------------------------------------------------------------
__global__ void final_kernel(float* __restrict__ out) {
    if (threadIdx.x == 0) {
        float s = 0.0f;
        int c = 0;
#pragma unroll
        for (int b = 0; b < RL_BLOCKS; b++) { s += g_blocksum[b]; c += g_blockcnt[b]; }
        out[0] = s / (float)(c > 0 ? c : 1);
    }
}

// ---------------------------------------------------------------------------
// Launch
// ---------------------------------------------------------------------------
extern "C" void kernel_launch(void* const* d_in, const int* in_sizes, int n_in,
                              void* d_out, int out_size) {
    const float* hidden = (const float*)d_in[0];
    const float* weight = (const float*)d_in[1];
    const long long* targets = (const long long*)d_in[2];
    float* out = (float*)d_out;

    cudaFuncSetAttribute(gemm_ce_kernel, cudaFuncAttributeMaxDynamicSharedMemorySize, SM_TOTAL);

    convert_kernel<<<2048, 256>>>(hidden, weight);
    gemm_ce_kernel<<<M_PAIRS * N_TILES * 2, 128, SM_TOTAL>>>(targets);
    row_loss_kernel<<<RL_BLOCKS, 256>>>(targets);
    final_kernel<<<1, 32>>>(out);
}

// round 5
// speedup vs baseline: 2.0608x; 2.0608x over previous
#include <cuda_runtime.h>
#include <cuda_bf16.h>
#include <cstdint>

// ---------------------------------------------------------------------------
// Problem constants
// ---------------------------------------------------------------------------
#define BT 4096
#define HDIM 2048
#define VOCAB 32000
#define TILE_M 128
#define TILE_N 512                         // per-CTA tile width (2 x N=256 MMAs)
#define K_CHUNK 64
#define N_KCHUNKS (HDIM / K_CHUNK)         // 32
#define M_TILES (BT / TILE_M)              // 32
#define N_TILES 63                         // 62 x 512 + 1 x 256 = 32000
#define IGNORE_INDEX (-100LL)
#define RL_BLOCKS 16

// idesc per N=256 MMA: dtype=F32(1<<4), atype=BF16(1<<7), btype=BF16(1<<10),
// N/8<<17, M/16<<24
#define MMA_IDESC ((1u << 4) | (1u << 7) | (1u << 10) | ((256 / 8) << 17) | ((TILE_M / 16) << 24))

// SMEM layout (dynamic)
#define SM_TMEMPTR 0
#define SM_BAR0 8
#define SM_BAR1 16
#define SM_A 1024                          // 2 x 16384  (128 rows x 128B)
#define SM_B (1024 + 2 * TILE_M * 128)     // 33792, 2 x 65536 (512 rows x 128B)
#define SM_TOTAL (SM_B + 2 * TILE_N * 128) // 164864 (~161KB) -> 1 CTA/SM

#if defined(__CUDA_ARCH_FEAT_SM103_ALL) || defined(__CUDA_ARCH_FEAT_SM100_ALL)
#define HAS_TCGEN05 1
#else
#define HAS_TCGEN05 0
#endif

// ---------------------------------------------------------------------------
// Device scratch (static __device__ arrays: allocation-guard-safe)
// ---------------------------------------------------------------------------
__device__ __nv_bfloat16 g_hid_bf[(size_t)BT * HDIM];
__device__ __nv_bfloat16 g_w_bf[(size_t)VOCAB * HDIM];
__device__ float g_partials[(size_t)N_TILES * BT];
__device__ float g_tgt[BT];
__device__ float g_blocksum[RL_BLOCKS];
__device__ int   g_blockcnt[RL_BLOCKS];

// ---------------------------------------------------------------------------
// PTX helpers
// ---------------------------------------------------------------------------
__device__ __forceinline__ uint32_t smem_to_u32(const void* p) {
    uint32_t a;
    asm("{ .reg .u64 t; cvta.to.shared.u64 t, %1; cvt.u32.u64 %0, t; }" : "=r"(a) : "l"(p));
    return a;
}
__device__ __forceinline__ uint32_t elect_one_pred() {
    uint32_t pred;
    asm volatile("{\n\t.reg .pred p;\n\telect.sync _|p, 0xFFFFFFFF;\n\tselp.b32 %0, 1, 0, p;\n\t}" : "=r"(pred));
    return pred;
}
#define TCGEN05_ALLOC(smem_addr, nCols) \
    asm volatile("tcgen05.alloc.cta_group::1.sync.aligned.shared::cta.b32 [%0], %1;" \
                 :: "r"((uint32_t)(smem_addr)), "r"((uint32_t)(nCols)) : "memory")
#define TCGEN05_DEALLOC(tmem_addr, nCols) \
    asm volatile("tcgen05.dealloc.cta_group::1.sync.aligned.b32 %0, %1;" :: "r"(tmem_addr), "r"((uint32_t)(nCols)))
#define TCGEN05_RELINQUISH() \
    asm volatile("tcgen05.relinquish_alloc_permit.cta_group::1.sync.aligned;")
#define TCGEN05_COMMIT(mbar) \
    asm volatile("tcgen05.commit.cta_group::1.mbarrier::arrive::one.shared::cluster.b64 [%0];" \
                 :: "r"((uint32_t)(mbar)) : "memory")
#define TCGEN05_FENCE_AFTER() asm volatile("tcgen05.fence::after_thread_sync;" ::: "memory")
#define TCGEN05_FENCE_BEFORE() asm volatile("tcgen05.fence::before_thread_sync;" ::: "memory")
#define TCGEN05_WAIT_LD() asm volatile("tcgen05.wait::ld.sync.aligned;" ::: "memory")
#define FENCE_PROXY_ASYNC_SHARED() asm volatile("fence.proxy.async.shared::cta;" ::: "memory")
#define MBARRIER_INIT(mbar, cnt) \
    asm volatile("mbarrier.init.shared.b64 [%0], %1;" :: "r"((uint32_t)(mbar)), "r"((uint32_t)(cnt)) : "memory")
#define MBARRIER_INVAL(mbar) \
    asm volatile("mbarrier.inval.shared.b64 [%0];" :: "r"((uint32_t)(mbar)) : "memory")
#define MBARRIER_WAIT_PARITY(mbar, parity) do {                                           \
    uint32_t _m = (uint32_t)(mbar); uint32_t _p = (uint32_t)(parity); uint32_t _d;        \
    asm volatile("{\n\t.reg .pred p;\n\t"                                                 \
        "mbarrier.try_wait.parity.acquire.cta.shared::cta.b64 p, [%1], %2;\n\t"           \
        "selp.b32 %0, 1, 0, p;\n\t}" : "=r"(_d) : "r"(_m), "r"(_p) : "memory");           \
    if (!_d) {                                                                            \
        asm volatile("{\n\t.reg .pred P1;\n\t"                                            \
            "WAIT_LOOP_%=:\n\t"                                                           \
            "mbarrier.try_wait.parity.acquire.cta.shared::cta.b64 P1, [%0], %1, 0x989680;\n\t" \
            "@P1 bra.uni WAIT_DONE_%=;\n\t"                                               \
            "bra.uni WAIT_LOOP_%=;\n\t"                                                   \
            "WAIT_DONE_%=:\n\t}" :: "r"(_m), "r"(_p) : "memory");                         \
    }                                                                                     \
} while (0)
#define TCGEN05_LD_32X32B_X32(r, tmem_addr) \
    asm volatile( \
        "tcgen05.ld.sync.aligned.32x32b.x32.b32 " \
        "{%0, %1, %2, %3, %4, %5, %6, %7, " \
        " %8, %9, %10, %11, %12, %13, %14, %15, " \
        " %16, %17, %18, %19, %20, %21, %22, %23, " \
        " %24, %25, %26, %27, %28, %29, %30, %31}, [%32];" \
        : "=r"((r)[0]),  "=r"((r)[1]),  "=r"((r)[2]),  "=r"((r)[3]), \
          "=r"((r)[4]),  "=r"((r)[5]),  "=r"((r)[6]),  "=r"((r)[7]), \
          "=r"((r)[8]),  "=r"((r)[9]),  "=r"((r)[10]), "=r"((r)[11]), \
          "=r"((r)[12]), "=r"((r)[13]), "=r"((r)[14]), "=r"((r)[15]), \
          "=r"((r)[16]), "=r"((r)[17]), "=r"((r)[18]), "=r"((r)[19]), \
          "=r"((r)[20]), "=r"((r)[21]), "=r"((r)[22]), "=r"((r)[23]), \
          "=r"((r)[24]), "=r"((r)[25]), "=r"((r)[26]), "=r"((r)[27]), \
          "=r"((r)[28]), "=r"((r)[29]), "=r"((r)[30]), "=r"((r)[31]) \
        : "r"(tmem_addr))

static constexpr uint64_t SMEM_DESC_BASE_SW128 =
    (uint64_t(2) << 61) | (uint64_t(1) << 46) | (uint64_t(64) << 32) | (uint64_t(1) << 16);
#define MAKE_SMEM_DESC(base_addr) (SMEM_DESC_BASE_SW128 | ((uint64_t)((base_addr) >> 4) & 0x3FFF))
#define SMEM_SWIZZLE_128B(off) ((off) ^ (((off) >> 3) & 0x70))

#if HAS_TCGEN05
__device__ __forceinline__ void mma_f16_ss(uint32_t d_tmem, uint64_t a_desc, uint64_t b_desc,
                                           uint32_t idesc, uint32_t enable_d) {
    asm volatile(
        "{\n\t.reg .pred p;\n\t"
        "setp.ne.u32 p, %5, 0;\n\t"
        "tcgen05.mma.cta_group::1.kind::f16 [%0], %1, %2, %3, {%4, %4, %4, %4}, p;\n\t}"
        :: "r"(d_tmem), "l"(a_desc), "l"(b_desc), "r"(idesc), "r"(0u), "r"(enable_d)
        : "memory");
}
#endif

// ---------------------------------------------------------------------------
// Kernel 1: fp32 -> bf16 conversion (halves GEMM traffic)
// ---------------------------------------------------------------------------
__global__ void convert_kernel(const float* __restrict__ hid, const float* __restrict__ w) {
    const size_t nh = (size_t)BT * HDIM / 4;
    const size_t nw = (size_t)VOCAB * HDIM / 4;
    const size_t total = nh + nw;
    size_t stride = (size_t)gridDim.x * blockDim.x;
    for (size_t i = (size_t)blockIdx.x * blockDim.x + threadIdx.x; i < total; i += stride) {
        const float4* src;
        __nv_bfloat16* dst;
        size_t j;
        if (i < nh) { src = (const float4*)hid; dst = g_hid_bf; j = i; }
        else        { src = (const float4*)w;   dst = g_w_bf;   j = i - nh; }
        float4 v = src[j];
        __nv_bfloat162 lo = __floats2bfloat162_rn(v.x, v.y);
        __nv_bfloat162 hi = __floats2bfloat162_rn(v.z, v.w);
        *(__nv_bfloat162*)(dst + j * 4)     = lo;
        *(__nv_bfloat162*)(dst + j * 4 + 2) = hi;
    }
}

// ---------------------------------------------------------------------------
// Kernel 2: cg1 tcgen05 bf16 GEMM, 128x512 tiles (two N=256 MMAs) + CE epilogue
// ---------------------------------------------------------------------------
__device__ __forceinline__ void load_tile_chunk(char* smem, int tid,
                                                const __nv_bfloat16* Ag,
                                                const __nv_bfloat16* Bg,
                                                int k0, int buf, int b_iters) {
    char* abase = smem + SM_A + buf * (TILE_M * 128);
    char* bbase = smem + SM_B + buf * (TILE_N * 128);
#pragma unroll
    for (int l = 0; l < 8; l++) {                 // A: 128 rows x 64 bf16
        int i = tid + l * 128;
        int row = i >> 3, c = i & 7;
        uint4 v = *(const uint4*)(Ag + (size_t)row * HDIM + k0 + c * 8);
        uint32_t off = row * 128 + c * 16;
        *(uint4*)(abase + SMEM_SWIZZLE_128B(off)) = v;
    }
#pragma unroll
    for (int l = 0; l < TILE_N / 16; l++) {       // B: up to 512 rows x 64 bf16
        if (l < b_iters) {
            int i = tid + l * 128;
            int row = i >> 3, c = i & 7;
            uint4 v = *(const uint4*)(Bg + (size_t)row * HDIM + k0 + c * 8);
            uint32_t off = row * 128 + c * 16;
            *(uint4*)(bbase + SMEM_SWIZZLE_128B(off)) = v;
        }
    }
}

__global__ void __launch_bounds__(128, 1)
gemm_ce_kernel(const long long* __restrict__ targets) {
    extern __shared__ char smem[];
    int tid = threadIdx.x;

    // consecutive blocks share the same weight (N) panel -> L2 reuse of B in a wave
    int n_tile = blockIdx.x / M_TILES;
    int m_tile = blockIdx.x % M_TILES;
    int m0 = m_tile * TILE_M;
    int n0 = n_tile * TILE_N;
    int nvalid = (n_tile == N_TILES - 1) ? (VOCAB - n0) : TILE_N;  // 512 or 256
    int b_iters = nvalid / 16;                                     // 32 or 16

#if HAS_TCGEN05
    uint32_t sb = smem_to_u32(smem);
    int wid = tid >> 5;

    if (wid == 0) {
        TCGEN05_ALLOC(sb + SM_TMEMPTR, 512);
        TCGEN05_RELINQUISH();
    }
    __syncthreads();
    uint32_t tmem;
    asm volatile("ld.shared.b32 %0, [%1];" : "=r"(tmem) : "r"(sb + SM_TMEMPTR));

    if (tid == 0) {
        MBARRIER_INIT(sb + SM_BAR0, 1);
        MBARRIER_INIT(sb + SM_BAR1, 1);
    }
    __syncthreads();

    const __nv_bfloat16* Ag = g_hid_bf + (size_t)m0 * HDIM;
    const __nv_bfloat16* Bg = g_w_bf + (size_t)n0 * HDIM;

    // prologue
    load_tile_chunk(smem, tid, Ag, Bg, 0, 0, b_iters);
    FENCE_PROXY_ASYNC_SHARED();
    __syncthreads();

    int ph0 = 0, ph1 = 0;
#pragma unroll 1
    for (int kc = 0; kc < N_KCHUNKS; kc++) {
        int cur = kc & 1;
        if (wid == 0) {
            if (elect_one_pred()) {
                uint64_t ad = MAKE_SMEM_DESC(sb + SM_A + cur * (TILE_M * 128));
                uint64_t bd0 = MAKE_SMEM_DESC(sb + SM_B + cur * (TILE_N * 128));
                uint64_t bd1 = MAKE_SMEM_DESC(sb + SM_B + cur * (TILE_N * 128) + 256 * 128);
#pragma unroll
                for (int s = 0; s < 4; s++) {   // 4 x K=16 within the 64-col chunk
                    uint32_t en = (kc > 0 || s > 0) ? 1u : 0u;
                    mma_f16_ss(tmem, ad + s * 2, bd0 + s * 2, MMA_IDESC, en);
                    if (nvalid == TILE_N)
                        mma_f16_ss(tmem + 256, ad + s * 2, bd1 + s * 2, MMA_IDESC, en);
                }
                TCGEN05_COMMIT(sb + (cur ? SM_BAR1 : SM_BAR0));
            }
        }
        // buffer cur^1 must be done being read by the previous MMA before refill
        if (kc >= 1) {
            if ((cur ^ 1) == 0) { MBARRIER_WAIT_PARITY(sb + SM_BAR0, ph0); ph0 ^= 1; }
            else                { MBARRIER_WAIT_PARITY(sb + SM_BAR1, ph1); ph1 ^= 1; }
        }
        if (kc + 1 < N_KCHUNKS) {
            load_tile_chunk(smem, tid, Ag, Bg, (kc + 1) * K_CHUNK, cur ^ 1, b_iters);
            FENCE_PROXY_ASYNC_SHARED();
        }
        __syncthreads();
    }
    MBARRIER_WAIT_PARITY(sb + SM_BAR1, ph1);   // last chunk (kc=31) on BAR1
    TCGEN05_FENCE_AFTER();

    // Epilogue: thread tid == output row (TMEM lane).
    long long t = targets[m0 + tid];
    float sum = 0.0f;
    float tval = 0.0f;
    int cmax = nvalid / 32;
#pragma unroll 1
    for (int c = 0; c < cmax; c++) {
        uint32_t regs[32];
        TCGEN05_LD_32X32B_X32(regs, tmem + c * 32);
        TCGEN05_WAIT_LD();
#pragma unroll
        for (int j = 0; j < 32; j++) {
            float v = __uint_as_float(regs[j]);
            sum += __expf(v);
            if ((long long)(n0 + c * 32 + j) == t) tval = v;
        }
    }
    TCGEN05_FENCE_BEFORE();
    g_partials[(size_t)n_tile * BT + m0 + tid] = sum;
    if (t >= (long long)n0 && t < (long long)(n0 + nvalid)) g_tgt[m0 + tid] = tval;

    __syncthreads();
    if (tid == 0) { MBARRIER_INVAL(sb + SM_BAR0); MBARRIER_INVAL(sb + SM_BAR1); }
    __syncthreads();
    if (wid == 0) TCGEN05_DEALLOC(tmem, 512);

#else  // ------- non-sm_103a fallback (PTX-JIT path only) --------------------
    __nv_bfloat16* As = (__nv_bfloat16*)smem;
    __nv_bfloat16* Bs = (__nv_bfloat16*)(smem + 16384);
    const __nv_bfloat16* Ag = g_hid_bf + (size_t)m0 * HDIM;

    long long t = targets[m0 + tid];
    float sum = 0.0f, tval = 0.0f;
    for (int cg = 0; cg < nvalid / 32; cg++) {
        float acc[32];
#pragma unroll
        for (int j = 0; j < 32; j++) acc[j] = 0.0f;
        const __nv_bfloat16* Bg = g_w_bf + (size_t)(n0 + cg * 32) * HDIM;
        for (int kc = 0; kc < N_KCHUNKS; kc++) {
            __syncthreads();
            int k0 = kc * K_CHUNK;
#pragma unroll
            for (int l = 0; l < 8; l++) {
                int i = tid + l * 128;
                int r2 = i >> 3, c = i & 7;
                *(uint4*)(As + r2 * 64 + c * 8) =
                    *(const uint4*)(Ag + (size_t)r2 * HDIM + k0 + c * 8);
            }
#pragma unroll
            for (int l = 0; l < 2; l++) {
                int i = tid + l * 128;
                int r2 = i >> 3, c = i & 7;
                *(uint4*)(Bs + r2 * 64 + c * 8) =
                    *(const uint4*)(Bg + (size_t)r2 * HDIM + k0 + c * 8);
            }
            __syncthreads();
            for (int k = 0; k < K_CHUNK; k++) {
                float a = __bfloat162float(As[tid * 64 + k]);
#pragma unroll
                for (int j = 0; j < 32; j++)
                    acc[j] += a * __bfloat162float(Bs[j * 64 + k]);
            }
        }
#pragma unroll
        for (int j = 0; j < 32; j++) {
            float v = acc[j];
            sum += __expf(v);
            if ((long long)(n0 + cg * 32 + j) == t) tval = v;
        }
    }
    g_partials[(size_t)n_tile * BT + m0 + tid] = sum;
    if (t >= (long long)n0 && t < (long long)(n0 + nvalid)) g_tgt[m0 + tid] = tval;
#endif
}

// ---------------------------------------------------------------------------
// Kernel 3a: per-row loss, whole-chip parallel, deterministic
// ---------------------------------------------------------------------------
__global__ void row_loss_kernel(const long long* __restrict__ targets) {
    __shared__ float sl[256];
    __shared__ int sc[256];
    int tid = threadIdx.x;
    int r = blockIdx.x * 256 + tid;

    float s = 0.0f;
#pragma unroll 7
    for (int nt = 0; nt < N_TILES; nt++) s += g_partials[(size_t)nt * BT + r];

    long long t = targets[r];
    bool valid = (t != IGNORE_INDEX);
    sl[tid] = valid ? (logf(s) - g_tgt[r]) : 0.0f;
    sc[tid] = valid ? 1 : 0;
    __syncthreads();
#pragma unroll
    for (int o = 128; o > 0; o >>= 1) {
        if (tid < o) { sl[tid] += sl[tid + o]; sc[tid] += sc[tid + o]; }
        __syncthreads();
    }
    if (tid == 0) { g_blocksum[blockIdx.x] = sl[0]; g_blockcnt[blockIdx.x] = sc[0]; }
}

// ---------------------------------------------------------------------------
// Kernel 3b: final scalar combine
// ---------------------------------------------------------------------------
__global__ void final_kernel(float* __restrict__ out) {
    if (threadIdx.x == 0) {
        float s = 0.0f;
        int c = 0;
#pragma unroll
        for (int b = 0; b < RL_BLOCKS; b++) { s += g_blocksum[b]; c += g_blockcnt[b]; }
        out[0] = s / (float)(c > 0 ? c : 1);
    }
}

// ---------------------------------------------------------------------------
// Launch
// ---------------------------------------------------------------------------
extern "C" void kernel_launch(void* const* d_in, const int* in_sizes, int n_in,
                              void* d_out, int out_size) {
    const float* hidden = (const float*)d_in[0];
    const float* weight = (const float*)d_in[1];
    const long long* targets = (const long long*)d_in[2];
    float* out = (float*)d_out;

    cudaFuncSetAttribute(gemm_ce_kernel, cudaFuncAttributeMaxDynamicSharedMemorySize, SM_TOTAL);

    convert_kernel<<<2048, 256>>>(hidden, weight);
    gemm_ce_kernel<<<M_TILES * N_TILES, 128, SM_TOTAL>>>(targets);
    row_loss_kernel<<<RL_BLOCKS, 256>>>(targets);
    final_kernel<<<1, 32>>>(out);
}

// round 6
// speedup vs baseline: 3.8898x; 1.8875x over previous
#include <cuda_runtime.h>
#include <cuda.h>
#include <cuda_bf16.h>
#include <cstdint>

// ---------------------------------------------------------------------------
// Problem constants
// ---------------------------------------------------------------------------
#define BT 4096
#define HDIM 2048
#define VOCAB 32000
#define TILE_M 128
#define TILE_N 512                         // per-CTA tile width (2 x N=256 MMAs)
#define K_CHUNK 64
#define N_KCHUNKS (HDIM / K_CHUNK)         // 32
#define M_TILES (BT / TILE_M)              // 32
#define N_TILES 63                         // 62 x 512 + 1 x 256 = 32000
#define IGNORE_INDEX (-100LL)
#define RL_BLOCKS 16

// idesc per N=256 MMA: dtype=F32(1<<4), atype=BF16(1<<7), btype=BF16(1<<10),
// N/8<<17, M/16<<24
#define MMA_IDESC ((1u << 4) | (1u << 7) | (1u << 10) | ((256 / 8) << 17) | ((TILE_M / 16) << 24))

// SMEM layout (dynamic)
#define SM_TMEMPTR 0
#define SM_F0 8
#define SM_F1 16
#define SM_M0 24
#define SM_M1 32
#define SM_A 1024                          // 2 x 16384  (128 rows x 128B)
#define SM_B (1024 + 2 * TILE_M * 128)     // 33792, 2 x 65536 (512 rows x 128B)
#define SM_TOTAL (SM_B + 2 * TILE_N * 128) // 164864 (~161KB) -> 1 CTA/SM

#define A_CHUNK_BYTES (TILE_M * 128)       // 16384
#define B_HALF_BYTES  (256 * 128)          // 32768

#if defined(__CUDA_ARCH_FEAT_SM103_ALL) || defined(__CUDA_ARCH_FEAT_SM100_ALL)
#define HAS_TCGEN05 1
#else
#define HAS_TCGEN05 0
#endif

// ---------------------------------------------------------------------------
// Device scratch (static __device__ arrays: allocation-guard-safe)
// ---------------------------------------------------------------------------
__device__ __nv_bfloat16 g_hid_bf[(size_t)BT * HDIM];
__device__ __nv_bfloat16 g_w_bf[(size_t)VOCAB * HDIM];
__device__ float g_partials[(size_t)N_TILES * BT];
__device__ float g_tgt[BT];
__device__ float g_blocksum[RL_BLOCKS];
__device__ int   g_blockcnt[RL_BLOCKS];

// ---------------------------------------------------------------------------
// PTX helpers
// ---------------------------------------------------------------------------
__device__ __forceinline__ uint32_t smem_to_u32(const void* p) {
    uint32_t a;
    asm("{ .reg .u64 t; cvta.to.shared.u64 t, %1; cvt.u32.u64 %0, t; }" : "=r"(a) : "l"(p));
    return a;
}
#define TCGEN05_ALLOC(smem_addr, nCols) \
    asm volatile("tcgen05.alloc.cta_group::1.sync.aligned.shared::cta.b32 [%0], %1;" \
                 :: "r"((uint32_t)(smem_addr)), "r"((uint32_t)(nCols)) : "memory")
#define TCGEN05_DEALLOC(tmem_addr, nCols) \
    asm volatile("tcgen05.dealloc.cta_group::1.sync.aligned.b32 %0, %1;" :: "r"(tmem_addr), "r"((uint32_t)(nCols)))
#define TCGEN05_RELINQUISH() \
    asm volatile("tcgen05.relinquish_alloc_permit.cta_group::1.sync.aligned;")
#define TCGEN05_COMMIT(mbar) \
    asm volatile("tcgen05.commit.cta_group::1.mbarrier::arrive::one.shared::cluster.b64 [%0];" \
                 :: "r"((uint32_t)(mbar)) : "memory")
#define TCGEN05_FENCE_AFTER() asm volatile("tcgen05.fence::after_thread_sync;" ::: "memory")
#define TCGEN05_FENCE_BEFORE() asm volatile("tcgen05.fence::before_thread_sync;" ::: "memory")
#define TCGEN05_WAIT_LD() asm volatile("tcgen05.wait::ld.sync.aligned;" ::: "memory")
#define MBARRIER_INIT(mbar, cnt) \
    asm volatile("mbarrier.init.shared.b64 [%0], %1;" :: "r"((uint32_t)(mbar)), "r"((uint32_t)(cnt)) : "memory")
#define MBARRIER_INVAL(mbar) \
    asm volatile("mbarrier.inval.shared.b64 [%0];" :: "r"((uint32_t)(mbar)) : "memory")
#define MBARRIER_EXPECT_TX(mbar, bytes) \
    asm volatile("mbarrier.arrive.expect_tx.shared.b64 _, [%0], %1;" \
                 :: "r"((uint32_t)(mbar)), "r"((uint32_t)(bytes)) : "memory")
#define MBARRIER_WAIT_PARITY(mbar, parity) do {                                           \
    uint32_t _m = (uint32_t)(mbar); uint32_t _p = (uint32_t)(parity); uint32_t _d;        \
    asm volatile("{\n\t.reg .pred p;\n\t"                                                 \
        "mbarrier.try_wait.parity.acquire.cta.shared::cta.b64 p, [%1], %2;\n\t"           \
        "selp.b32 %0, 1, 0, p;\n\t}" : "=r"(_d) : "r"(_m), "r"(_p) : "memory");           \
    if (!_d) {                                                                            \
        asm volatile("{\n\t.reg .pred P1;\n\t"                                            \
            "WAIT_LOOP_%=:\n\t"                                                           \
            "mbarrier.try_wait.parity.acquire.cta.shared::cta.b64 P1, [%0], %1, 0x989680;\n\t" \
            "@P1 bra.uni WAIT_DONE_%=;\n\t"                                               \
            "bra.uni WAIT_LOOP_%=;\n\t"                                                   \
            "WAIT_DONE_%=:\n\t}" :: "r"(_m), "r"(_p) : "memory");                         \
    }                                                                                     \
} while (0)
#define TMA_LOAD_2D(smem_addr, map_ptr, cx, cy, mbar) \
    asm volatile("cp.async.bulk.tensor.2d.shared::cta.global.tile.mbarrier::complete_tx::bytes " \
                 "[%0], [%1, {%2, %3}], [%4];" \
                 :: "r"((uint32_t)(smem_addr)), "l"(map_ptr), "r"((int32_t)(cx)), \
                    "r"((int32_t)(cy)), "r"((uint32_t)(mbar)) : "memory")
#define TCGEN05_LD_32X32B_X32(r, tmem_addr) \
    asm volatile( \
        "tcgen05.ld.sync.aligned.32x32b.x32.b32 " \
        "{%0, %1, %2, %3, %4, %5, %6, %7, " \
        " %8, %9, %10, %11, %12, %13, %14, %15, " \
        " %16, %17, %18, %19, %20, %21, %22, %23, " \
        " %24, %25, %26, %27, %28, %29, %30, %31}, [%32];" \
        : "=r"((r)[0]),  "=r"((r)[1]),  "=r"((r)[2]),  "=r"((r)[3]), \
          "=r"((r)[4]),  "=r"((r)[5]),  "=r"((r)[6]),  "=r"((r)[7]), \
          "=r"((r)[8]),  "=r"((r)[9]),  "=r"((r)[10]), "=r"((r)[11]), \
          "=r"((r)[12]), "=r"((r)[13]), "=r"((r)[14]), "=r"((r)[15]), \
          "=r"((r)[16]), "=r"((r)[17]), "=r"((r)[18]), "=r"((r)[19]), \
          "=r"((r)[20]), "=r"((r)[21]), "=r"((r)[22]), "=r"((r)[23]), \
          "=r"((r)[24]), "=r"((r)[25]), "=r"((r)[26]), "=r"((r)[27]), \
          "=r"((r)[28]), "=r"((r)[29]), "=r"((r)[30]), "=r"((r)[31]) \
        : "r"(tmem_addr))

static constexpr uint64_t SMEM_DESC_BASE_SW128 =
    (uint64_t(2) << 61) | (uint64_t(1) << 46) | (uint64_t(64) << 32) | (uint64_t(1) << 16);
#define MAKE_SMEM_DESC(base_addr) (SMEM_DESC_BASE_SW128 | ((uint64_t)((base_addr) >> 4) & 0x3FFF))

#if HAS_TCGEN05
__device__ __forceinline__ void mma_f16_ss(uint32_t d_tmem, uint64_t a_desc, uint64_t b_desc,
                                           uint32_t idesc, uint32_t enable_d) {
    asm volatile(
        "{\n\t.reg .pred p;\n\t"
        "setp.ne.u32 p, %5, 0;\n\t"
        "tcgen05.mma.cta_group::1.kind::f16 [%0], %1, %2, %3, {%4, %4, %4, %4}, p;\n\t}"
        :: "r"(d_tmem), "l"(a_desc), "l"(b_desc), "r"(idesc), "r"(0u), "r"(enable_d)
        : "memory");
}
#endif

// ---------------------------------------------------------------------------
// Kernel 1: fp32 -> bf16 conversion (halves GEMM traffic)
// ---------------------------------------------------------------------------
__global__ void convert_kernel(const float* __restrict__ hid, const float* __restrict__ w) {
    const size_t nh = (size_t)BT * HDIM / 4;
    const size_t nw = (size_t)VOCAB * HDIM / 4;
    const size_t total = nh + nw;
    size_t stride = (size_t)gridDim.x * blockDim.x;
    for (size_t i = (size_t)blockIdx.x * blockDim.x + threadIdx.x; i < total; i += stride) {
        const float4* src;
        __nv_bfloat16* dst;
        size_t j;
        if (i < nh) { src = (const float4*)hid; dst = g_hid_bf; j = i; }
        else        { src = (const float4*)w;   dst = g_w_bf;   j = i - nh; }
        float4 v = src[j];
        __nv_bfloat162 lo = __floats2bfloat162_rn(v.x, v.y);
        __nv_bfloat162 hi = __floats2bfloat162_rn(v.z, v.w);
        *(__nv_bfloat162*)(dst + j * 4)     = lo;
        *(__nv_bfloat162*)(dst + j * 4 + 2) = hi;
    }
}

// ---------------------------------------------------------------------------
// Kernel 2: TMA-fed cg1 tcgen05 GEMM, 128x512 tiles + fused CE epilogue.
// Single driver thread (tid 0) owns the whole producer/consumer pipeline;
// fills come from the TMA engine (no thread-MLP limit), depth-2 buffered.
// ---------------------------------------------------------------------------
__global__ void __launch_bounds__(128, 1)
gemm_ce_kernel(const __grid_constant__ CUtensorMap tma_a,
               const __grid_constant__ CUtensorMap tma_b,
               const long long* __restrict__ targets) {
    extern __shared__ __align__(1024) char smem[];
    int tid = threadIdx.x;

    // consecutive blocks share the same weight (N) panel -> L2 reuse of B in a wave
    int n_tile = blockIdx.x / M_TILES;
    int m_tile = blockIdx.x % M_TILES;
    int m0 = m_tile * TILE_M;
    int n0 = n_tile * TILE_N;
    int nvalid = (n_tile == N_TILES - 1) ? (VOCAB - n0) : TILE_N;  // 512 or 256

#if HAS_TCGEN05
    uint32_t sb = smem_to_u32(smem);
    int wid = tid >> 5;

    if (wid == 0) {
        TCGEN05_ALLOC(sb + SM_TMEMPTR, 512);
        TCGEN05_RELINQUISH();
    }
    __syncthreads();
    uint32_t tmem;
    asm volatile("ld.shared.b32 %0, [%1];" : "=r"(tmem) : "r"(sb + SM_TMEMPTR));

    if (tid == 0) {
        MBARRIER_INIT(sb + SM_F0, 1);
        MBARRIER_INIT(sb + SM_F1, 1);
        MBARRIER_INIT(sb + SM_M0, 1);
        MBARRIER_INIT(sb + SM_M1, 1);
    }
    __syncthreads();

    if (tid == 0) {
        const uint32_t bytes = A_CHUNK_BYTES + ((nvalid == TILE_N) ? 2 : 1) * B_HALF_BYTES;
        const bool full = (nvalid == TILE_N);

        // prologue: fill both buffers with chunks 0 and 1
#pragma unroll
        for (int p = 0; p < 2; p++) {
            uint32_t fbar = sb + (p ? SM_F1 : SM_F0);
            uint32_t abuf = sb + SM_A + p * A_CHUNK_BYTES;
            uint32_t bbuf = sb + SM_B + p * (2 * B_HALF_BYTES);
            MBARRIER_EXPECT_TX(fbar, bytes);
            TMA_LOAD_2D(abuf, &tma_a, p * K_CHUNK, m0, fbar);
            TMA_LOAD_2D(bbuf, &tma_b, p * K_CHUNK, n0, fbar);
            if (full) TMA_LOAD_2D(bbuf + B_HALF_BYTES, &tma_b, p * K_CHUNK, n0 + 256, fbar);
        }

        int phf0 = 0, phf1 = 0, phm0 = 0, phm1 = 0;
#pragma unroll 1
        for (int kc = 0; kc < N_KCHUNKS; kc++) {
            int cur = kc & 1;
            // wait fill of buffer cur
            if (cur == 0) { MBARRIER_WAIT_PARITY(sb + SM_F0, phf0); phf0 ^= 1; }
            else          { MBARRIER_WAIT_PARITY(sb + SM_F1, phf1); phf1 ^= 1; }

            uint64_t ad  = MAKE_SMEM_DESC(sb + SM_A + cur * A_CHUNK_BYTES);
            uint64_t bd0 = MAKE_SMEM_DESC(sb + SM_B + cur * (2 * B_HALF_BYTES));
            uint64_t bd1 = bd0 + (B_HALF_BYTES >> 4);   // +256 rows in 16B units
#pragma unroll
            for (int s = 0; s < 4; s++) {               // 4 x K=16 per 64-col chunk
                uint32_t en = (kc > 0 || s > 0) ? 1u : 0u;
                mma_f16_ss(tmem, ad + s * 2, bd0 + s * 2, MMA_IDESC, en);
                if (full)
                    mma_f16_ss(tmem + 256, ad + s * 2, bd1 + s * 2, MMA_IDESC, en);
            }
            TCGEN05_COMMIT(sb + (cur ? SM_M1 : SM_M0));

            if (kc + 2 < N_KCHUNKS) {
                // buffer cur may be refilled only after MMA(kc) finished reading it
                if (cur == 0) { MBARRIER_WAIT_PARITY(sb + SM_M0, phm0); phm0 ^= 1; }
                else          { MBARRIER_WAIT_PARITY(sb + SM_M1, phm1); phm1 ^= 1; }
                uint32_t fbar = sb + (cur ? SM_F1 : SM_F0);
                uint32_t abuf = sb + SM_A + cur * A_CHUNK_BYTES;
                uint32_t bbuf = sb + SM_B + cur * (2 * B_HALF_BYTES);
                int k0 = (kc + 2) * K_CHUNK;
                MBARRIER_EXPECT_TX(fbar, bytes);
                TMA_LOAD_2D(abuf, &tma_a, k0, m0, fbar);
                TMA_LOAD_2D(bbuf, &tma_b, k0, n0, fbar);
                if (full) TMA_LOAD_2D(bbuf + B_HALF_BYTES, &tma_b, k0, n0 + 256, fbar);
            }
        }
        // outstanding MMA completions: chunk 30 (M0), chunk 31 (M1)
        MBARRIER_WAIT_PARITY(sb + SM_M0, phm0);
        MBARRIER_WAIT_PARITY(sb + SM_M1, phm1);
    }
    __syncthreads();
    TCGEN05_FENCE_AFTER();

    // Epilogue: thread tid == output row (TMEM lane).
    long long t = targets[m0 + tid];
    float sum = 0.0f;
    float tval = 0.0f;
    int cmax = nvalid / 32;
#pragma unroll 1
    for (int c = 0; c < cmax; c++) {
        uint32_t regs[32];
        TCGEN05_LD_32X32B_X32(regs, tmem + c * 32);
        TCGEN05_WAIT_LD();
#pragma unroll
        for (int j = 0; j < 32; j++) {
            float v = __uint_as_float(regs[j]);
            sum += __expf(v);
            if ((long long)(n0 + c * 32 + j) == t) tval = v;
        }
    }
    TCGEN05_FENCE_BEFORE();
    g_partials[(size_t)n_tile * BT + m0 + tid] = sum;
    if (t >= (long long)n0 && t < (long long)(n0 + nvalid)) g_tgt[m0 + tid] = tval;

    __syncthreads();
    if (tid == 0) {
        MBARRIER_INVAL(sb + SM_F0);
        MBARRIER_INVAL(sb + SM_F1);
        MBARRIER_INVAL(sb + SM_M0);
        MBARRIER_INVAL(sb + SM_M1);
    }
    __syncthreads();
    if (wid == 0) TCGEN05_DEALLOC(tmem, 512);

#else  // ------- non-sm_103a fallback (PTX-JIT path only) --------------------
    __nv_bfloat16* As = (__nv_bfloat16*)smem;
    __nv_bfloat16* Bs = (__nv_bfloat16*)(smem + 16384);
    const __nv_bfloat16* Ag = g_hid_bf + (size_t)m0 * HDIM;

    long long t = targets[m0 + tid];
    float sum = 0.0f, tval = 0.0f;
    for (int cg = 0; cg < nvalid / 32; cg++) {
        float acc[32];
#pragma unroll
        for (int j = 0; j < 32; j++) acc[j] = 0.0f;
        const __nv_bfloat16* Bg = g_w_bf + (size_t)(n0 + cg * 32) * HDIM;
        for (int kc = 0; kc < N_KCHUNKS; kc++) {
            __syncthreads();
            int k0 = kc * K_CHUNK;
#pragma unroll
            for (int l = 0; l < 8; l++) {
                int i = tid + l * 128;
                int r2 = i >> 3, c = i & 7;
                *(uint4*)(As + r2 * 64 + c * 8) =
                    *(const uint4*)(Ag + (size_t)r2 * HDIM + k0 + c * 8);
            }
#pragma unroll
            for (int l = 0; l < 2; l++) {
                int i = tid + l * 128;
                int r2 = i >> 3, c = i & 7;
                *(uint4*)(Bs + r2 * 64 + c * 8) =
                    *(const uint4*)(Bg + (size_t)r2 * HDIM + k0 + c * 8);
            }
            __syncthreads();
            for (int k = 0; k < K_CHUNK; k++) {
                float a = __bfloat162float(As[tid * 64 + k]);
#pragma unroll
                for (int j = 0; j < 32; j++)
                    acc[j] += a * __bfloat162float(Bs[j * 64 + k]);
            }
        }
#pragma unroll
        for (int j = 0; j < 32; j++) {
            float v = acc[j];
            sum += __expf(v);
            if ((long long)(n0 + cg * 32 + j) == t) tval = v;
        }
    }
    g_partials[(size_t)n_tile * BT + m0 + tid] = sum;
    if (t >= (long long)n0 && t < (long long)(n0 + nvalid)) g_tgt[m0 + tid] = tval;
#endif
}

// ---------------------------------------------------------------------------
// Kernel 3a: per-row loss, whole-chip parallel, deterministic
// ---------------------------------------------------------------------------
__global__ void row_loss_kernel(const long long* __restrict__ targets) {
    __shared__ float sl[256];
    __shared__ int sc[256];
    int tid = threadIdx.x;
    int r = blockIdx.x * 256 + tid;

    float s = 0.0f;
#pragma unroll 7
    for (int nt = 0; nt < N_TILES; nt++) s += g_partials[(size_t)nt * BT + r];

    long long t = targets[r];
    bool valid = (t != IGNORE_INDEX);
    sl[tid] = valid ? (logf(s) - g_tgt[r]) : 0.0f;
    sc[tid] = valid ? 1 : 0;
    __syncthreads();
#pragma unroll
    for (int o = 128; o > 0; o >>= 1) {
        if (tid < o) { sl[tid] += sl[tid + o]; sc[tid] += sc[tid + o]; }
        __syncthreads();
    }
    if (tid == 0) { g_blocksum[blockIdx.x] = sl[0]; g_blockcnt[blockIdx.x] = sc[0]; }
}

// ---------------------------------------------------------------------------
// Kernel 3b: final scalar combine
// ---------------------------------------------------------------------------
__global__ void final_kernel(float* __restrict__ out) {
    if (threadIdx.x == 0) {
        float s = 0.0f;
        int c = 0;
#pragma unroll
        for (int b = 0; b < RL_BLOCKS; b++) { s += g_blocksum[b]; c += g_blockcnt[b]; }
        out[0] = s / (float)(c > 0 ? c : 1);
    }
}

// ---------------------------------------------------------------------------
// Host: tensor-map construction via driver entry point (no -lcuda needed)
// ---------------------------------------------------------------------------
typedef CUresult (*tmap_encode_fn)(
    CUtensorMap*, CUtensorMapDataType, cuuint32_t, void*,
    const cuuint64_t*, const cuuint64_t*, const cuuint32_t*, const cuuint32_t*,
    CUtensorMapInterleave, CUtensorMapSwizzle, CUtensorMapL2promotion,
    CUtensorMapFloatOOBfill);

extern "C" void kernel_launch(void* const* d_in, const int* in_sizes, int n_in,
                              void* d_out, int out_size) {
    const float* hidden = (const float*)d_in[0];
    const float* weight = (const float*)d_in[1];
    const long long* targets = (const long long*)d_in[2];
    float* out = (float*)d_out;

    cudaFuncSetAttribute(gemm_ce_kernel, cudaFuncAttributeMaxDynamicSharedMemorySize, SM_TOTAL);

    // Resolve scratch symbol addresses + the tensor-map encoder.
    void* hid_bf_ptr = nullptr;
    void* w_bf_ptr = nullptr;
    cudaGetSymbolAddress(&hid_bf_ptr, g_hid_bf);
    cudaGetSymbolAddress(&w_bf_ptr, g_w_bf);

    tmap_encode_fn encode = nullptr;
    cudaDriverEntryPointQueryResult qres;
    cudaGetDriverEntryPoint("cuTensorMapEncodeTiled", (void**)&encode,
                            cudaEnableDefault, &qres);

    CUtensorMap tma_a, tma_b;
    {
        cuuint64_t dims[2] = {(cuuint64_t)HDIM, (cuuint64_t)BT};
        cuuint64_t strides[1] = {(cuuint64_t)HDIM * 2};
        cuuint32_t box[2] = {K_CHUNK, TILE_M};      // 64 bf16 = 128B rows (SW128), 128 rows
        cuuint32_t es[2] = {1, 1};
        encode(&tma_a, CU_TENSOR_MAP_DATA_TYPE_BFLOAT16, 2, hid_bf_ptr,
               dims, strides, box, es,
               CU_TENSOR_MAP_INTERLEAVE_NONE, CU_TENSOR_MAP_SWIZZLE_128B,
               CU_TENSOR_MAP_L2_PROMOTION_L2_128B, CU_TENSOR_MAP_FLOAT_OOB_FILL_NONE);
    }
    {
        cuuint64_t dims[2] = {(cuuint64_t)HDIM, (cuuint64_t)VOCAB};
        cuuint64_t strides[1] = {(cuuint64_t)HDIM * 2};
        cuuint32_t box[2] = {K_CHUNK, 256};         // B loaded as two 256-row halves
        cuuint32_t es[2] = {1, 1};
        encode(&tma_b, CU_TENSOR_MAP_DATA_TYPE_BFLOAT16, 2, w_bf_ptr,
               dims, strides, box, es,
               CU_TENSOR_MAP_INTERLEAVE_NONE, CU_TENSOR_MAP_SWIZZLE_128B,
               CU_TENSOR_MAP_L2_PROMOTION_L2_128B, CU_TENSOR_MAP_FLOAT_OOB_FILL_NONE);
    }

    convert_kernel<<<2048, 256>>>(hidden, weight);
    gemm_ce_kernel<<<M_TILES * N_TILES, 128, SM_TOTAL>>>(tma_a, tma_b, targets);
    row_loss_kernel<<<RL_BLOCKS, 256>>>(targets);
    final_kernel<<<1, 32>>>(out);
}